// round 2
// baseline (speedup 1.0000x reference)
#include <cuda_runtime.h>
#include <math.h>

// ---------------- constants ----------------
#define BATCH 32
#define NA 3
#define NC 80

#define H0 80
#define W0 80
#define H1 40
#define W1 40
#define H2 20
#define W2 20

#define M0 (BATCH*NA*H0*W0)   // 614400
#define M1 (BATCH*NA*H1*W1)   // 153600
#define M2 (BATCH*NA*H2*W2)   //  38400
#define MTOT (M0+M1+M2)       // 806400

#define N0 6000
#define N1 4000
#define N2 2000
#define NTGT_TOT (N0+N1+N2)   // 12000

#define OBJ0 4.0f
#define OBJ1 1.0f
#define OBJ2 0.4f

#define EPSV 1e-7f

// ---------------- scratch (no allocations allowed) ----------------
__device__ float  g_tobj[MTOT];
__device__ double g_acc[3];   // 0: lbox, 1: lobj, 2: lcls

// ---------------- helpers ----------------
__device__ __forceinline__ float bce_term(float x, float t) {
    // max(x,0) - x*t + log1p(exp(-|x|))
    return fmaxf(x, 0.f) - x * t + log1pf(expf(-fabsf(x)));
}
__device__ __forceinline__ float sigmoidf_(float x) {
    return 1.f / (1.f + expf(-x));
}

__device__ __forceinline__ float ciou(float cx1, float cy1, float w1, float h1,
                                      float cx2, float cy2, float w2, float h2) {
    // follow reference op order exactly (fp32)
    float x1a = cx1 - w1 * 0.5f, y1a = cy1 - h1 * 0.5f;
    float x2a = cx1 + w1 * 0.5f, y2a = cy1 + h1 * 0.5f;
    float x1b = cx2 - w2 * 0.5f, y1b = cy2 - h2 * 0.5f;
    float x2b = cx2 + w2 * 0.5f, y2b = cy2 + h2 * 0.5f;

    float iw = fmaxf(fminf(x2a, x2b) - fmaxf(x1a, x1b), 0.f);
    float ih = fmaxf(fminf(y2a, y2b) - fmaxf(y1a, y1b), 0.f);
    float inter = iw * ih;
    float uni = (x2a - x1a) * (y2a - y1a) + (x2b - x1b) * (y2b - y1b) - inter;
    float iou = inter / (uni + EPSV);

    float cw = fmaxf(x2a, x2b) - fminf(x1a, x1b);
    float ch = fmaxf(y2a, y2b) - fminf(y1a, y1b);
    float diag = cw * cw + ch * ch + EPSV;
    float dx = (x1a + x2a) * 0.5f - (x1b + x2b) * 0.5f;
    float dy = (y1a + y2a) * 0.5f - (y1b + y2b) * 0.5f;
    float cent = dx * dx + dy * dy;

    float at = atanf((x2a - x1a) / (y2a - y1a + EPSV))
             - atanf((x2b - x1b) / (y2b - y1b + EPSV));
    const float C4PI2 = 4.0f / (float)(M_PI * M_PI);
    float v = C4PI2 * at * at;
    float alpha = v / (v - iou + 1.f + EPSV);
    return iou - (cent / diag + v * alpha);
}

// ---------------- kernel 0: zero scratch + accumulators ----------------
__global__ void k_zero() {
    int i = blockIdx.x * blockDim.x + threadIdx.x;
    if (i < MTOT) g_tobj[i] = 0.f;
    if (i < 3) g_acc[i] = 0.0;
}

// ---------------- kernel 1: per-target gather (lbox, lcls, tobj scatter) ----
struct ScaleT {
    const float* box;   // [B,A,H,W,4]
    const float* cls;   // [B,A,H,W,80]
    const float* tbox;  // [n,4]
    const float* anc;   // [n,2]
    const int *b, *a, *gy, *gx, *tcls;
    int H, W;
    int tobj_off;
    float inv_n;        // 1/n
    float inv_ncls;     // 1/(n*80)
};

__global__ void k_targets(ScaleT s0, ScaleT s1, ScaleT s2) {
    int gw   = (blockIdx.x * blockDim.x + threadIdx.x) >> 5;
    int lane = threadIdx.x & 31;
    if (gw >= NTGT_TOT) return;

    ScaleT s; int t;
    if (gw < N0)            { s = s0; t = gw; }
    else if (gw < N0 + N1)  { s = s1; t = gw - N0; }
    else                    { s = s2; t = gw - N0 - N1; }

    int base = ((s.b[t] * NA + s.a[t]) * s.H + s.gy[t]) * s.W + s.gx[t];

    // ---- classification BCE across 80 classes (warp-parallel) ----
    int tc = s.tcls[t];
    const float* crow = s.cls + (size_t)base * NC;
    float csum = 0.f;
    #pragma unroll
    for (int c = lane; c < NC; c += 32)
        csum += bce_term(crow[c], (c == tc) ? 1.f : 0.f);
    #pragma unroll
    for (int o = 16; o; o >>= 1)
        csum += __shfl_down_sync(0xffffffffu, csum, o);

    if (lane == 0) {
        // ---- box: decode + CIoU ----
        const float* br = s.box + (size_t)base * 4;
        float px = sigmoidf_(br[0]) * 2.f - 0.5f;
        float py = sigmoidf_(br[1]) * 2.f - 0.5f;
        float sw = sigmoidf_(br[2]) * 2.f;
        float sh = sigmoidf_(br[3]) * 2.f;
        float pw = sw * sw * s.anc[2 * t + 0];
        float ph = sh * sh * s.anc[2 * t + 1];

        const float* tb = s.tbox + 4 * t;
        float ci = ciou(px, py, pw, ph, tb[0], tb[1], tb[2], tb[3]);

        g_tobj[s.tobj_off + base] = fmaxf(ci, 0.f);
        atomicAdd(&g_acc[0], (double)((1.f - ci) * s.inv_n));
        atomicAdd(&g_acc[2], (double)(csum * s.inv_ncls));
    }
}

// ---------------- kernel 2: dense objectness BCE ----------------
__global__ void k_obj(const float* __restrict__ cnf0,
                      const float* __restrict__ cnf1,
                      const float* __restrict__ cnf2) {
    int i = blockIdx.x * blockDim.x + threadIdx.x;
    float v = 0.f;
    if (i < MTOT) {
        float x, w;
        if (i < M0)            { x = cnf0[i];            w = OBJ0 / (float)M0; }
        else if (i < M0 + M1)  { x = cnf1[i - M0];       w = OBJ1 / (float)M1; }
        else                   { x = cnf2[i - M0 - M1];  w = OBJ2 / (float)M2; }
        v = bce_term(x, g_tobj[i]) * w;
    }
    // block reduction
    #pragma unroll
    for (int o = 16; o; o >>= 1)
        v += __shfl_down_sync(0xffffffffu, v, o);
    __shared__ float sm[8];
    if ((threadIdx.x & 31) == 0) sm[threadIdx.x >> 5] = v;
    __syncthreads();
    if (threadIdx.x < 8) {
        float b = sm[threadIdx.x];
        #pragma unroll
        for (int o = 4; o; o >>= 1)
            b += __shfl_down_sync(0xffu, b, o);
        if (threadIdx.x == 0) atomicAdd(&g_acc[1], (double)b);
    }
}

// ---------------- kernel 3: finalize ----------------
__global__ void k_final(float* out) {
    out[0] = (float)(g_acc[0] * 0.05 * 32.0);
    out[1] = (float)(g_acc[1] * 0.70 * 32.0);
    out[2] = (float)(g_acc[2] * 0.30 * 32.0);
}

// ---------------- launch ----------------
extern "C" void kernel_launch(void* const* d_in, const int* in_sizes, int n_in,
                              void* d_out, int out_size) {
    // Two possible metadata orderings; disambiguate via in_sizes[3]:
    //  (A) reference-arg order:
    //      [box0,cnf0,cls0,tbox0,anc0, box1,..., box2,...,
    //       b0,a0,gy0,gx0,tcls0, b1,..., b2,...]
    //      -> in_sizes[3] == 24000 (tbox0 = 6000*4)
    //  (B) setup_inputs insertion order, per scale:
    //      [box,cnf,cls,b,a,gy,gx,tcls,tbox,anc] x 3
    //      -> in_sizes[3] == 6000 (b0)
    const float *box[3], *cnf[3], *cls[3], *tbox[3], *anc[3];
    const int *bi[3], *ai[3], *gyi[3], *gxi[3], *tclsi[3];

    bool orderA = (n_in > 3 && in_sizes[3] == 24000);
    if (orderA) {
        for (int i = 0; i < 3; i++) {
            int f = 5 * i;       // float group base
            int g = 15 + 5 * i;  // int group base
            box[i]   = (const float*)d_in[f + 0];
            cnf[i]   = (const float*)d_in[f + 1];
            cls[i]   = (const float*)d_in[f + 2];
            tbox[i]  = (const float*)d_in[f + 3];
            anc[i]   = (const float*)d_in[f + 4];
            bi[i]    = (const int*)d_in[g + 0];
            ai[i]    = (const int*)d_in[g + 1];
            gyi[i]   = (const int*)d_in[g + 2];
            gxi[i]   = (const int*)d_in[g + 3];
            tclsi[i] = (const int*)d_in[g + 4];
        }
    } else {
        for (int i = 0; i < 3; i++) {
            int p = 10 * i;
            box[i]   = (const float*)d_in[p + 0];
            cnf[i]   = (const float*)d_in[p + 1];
            cls[i]   = (const float*)d_in[p + 2];
            bi[i]    = (const int*)d_in[p + 3];
            ai[i]    = (const int*)d_in[p + 4];
            gyi[i]   = (const int*)d_in[p + 5];
            gxi[i]   = (const int*)d_in[p + 6];
            tclsi[i] = (const int*)d_in[p + 7];
            tbox[i]  = (const float*)d_in[p + 8];
            anc[i]   = (const float*)d_in[p + 9];
        }
    }

    ScaleT s0 { box[0], cls[0], tbox[0], anc[0], bi[0], ai[0], gyi[0], gxi[0], tclsi[0],
                H0, W0, 0,          1.f / N0, 1.f / (N0 * (float)NC) };
    ScaleT s1 { box[1], cls[1], tbox[1], anc[1], bi[1], ai[1], gyi[1], gxi[1], tclsi[1],
                H1, W1, M0,         1.f / N1, 1.f / (N1 * (float)NC) };
    ScaleT s2 { box[2], cls[2], tbox[2], anc[2], bi[2], ai[2], gyi[2], gxi[2], tclsi[2],
                H2, W2, M0 + M1,    1.f / N2, 1.f / (N2 * (float)NC) };

    const int TPB = 256;
    k_zero<<<(MTOT + TPB - 1) / TPB, TPB>>>();
    k_targets<<<(NTGT_TOT * 32 + TPB - 1) / TPB, TPB>>>(s0, s1, s2);
    k_obj<<<(MTOT + TPB - 1) / TPB, TPB>>>(cnf[0], cnf[1], cnf[2]);
    k_final<<<1, 1>>>((float*)d_out);
}

// round 3
// speedup vs baseline: 2.3477x; 2.3477x over previous
#include <cuda_runtime.h>
#include <math.h>

// ---------------- constants ----------------
#define BATCH 32
#define NA 3
#define NC 80

#define H0 80
#define W0 80
#define H1 40
#define W1 40
#define H2 20
#define W2 20

#define M0 (BATCH*NA*H0*W0)   // 614400
#define M1 (BATCH*NA*H1*W1)   // 153600
#define M2 (BATCH*NA*H2*W2)   //  38400
#define MTOT (M0+M1+M2)       // 806400
#define QTOT (MTOT/4)         // 201600 float4s

#define N0 6000
#define N1 4000
#define N2 2000
#define NTGT_TOT (N0+N1+N2)   // 12000

#define OBJ0 4.0f
#define OBJ1 1.0f
#define OBJ2 0.4f

#define EPSV 1e-7f

#define TGT_BLOCKS (NTGT_TOT/8)            // 1500 (8 warps/block, 1 target/warp)
#define OBJ_BLOCKS ((QTOT + 255) / 256)    // 788

// ---------------- scratch (no allocations allowed) ----------------
// g_tobj: zero-initialized at module load; every run self-restores it to zero
// via atomicExch claims in k_obj. No dense zeroing pass needed.
__device__ float g_tobj[MTOT];
__device__ float g_pb[TGT_BLOCKS];   // per-block lbox partials (already / n)
__device__ float g_pc[TGT_BLOCKS];   // per-block lcls partials (already / (n*80))
__device__ float g_po[OBJ_BLOCKS];   // per-block lobj partials (already * obj_scale / M)

// ---------------- helpers ----------------
__device__ __forceinline__ float softplus_(float x) {
    // bce(x, 0) = max(x,0) + log1p(exp(-|x|))
    return fmaxf(x, 0.f) + log1pf(expf(-fabsf(x)));
}
__device__ __forceinline__ float bce_term(float x, float t) {
    return fmaxf(x, 0.f) - x * t + log1pf(expf(-fabsf(x)));
}
__device__ __forceinline__ float sigmoidf_(float x) {
    return 1.f / (1.f + expf(-x));
}

__device__ __forceinline__ float ciou(float cx1, float cy1, float w1, float h1,
                                      float cx2, float cy2, float w2, float h2) {
    float x1a = cx1 - w1 * 0.5f, y1a = cy1 - h1 * 0.5f;
    float x2a = cx1 + w1 * 0.5f, y2a = cy1 + h1 * 0.5f;
    float x1b = cx2 - w2 * 0.5f, y1b = cy2 - h2 * 0.5f;
    float x2b = cx2 + w2 * 0.5f, y2b = cy2 + h2 * 0.5f;

    float iw = fmaxf(fminf(x2a, x2b) - fmaxf(x1a, x1b), 0.f);
    float ih = fmaxf(fminf(y2a, y2b) - fmaxf(y1a, y1b), 0.f);
    float inter = iw * ih;
    float uni = (x2a - x1a) * (y2a - y1a) + (x2b - x1b) * (y2b - y1b) - inter;
    float iou = inter / (uni + EPSV);

    float cw = fmaxf(x2a, x2b) - fminf(x1a, x1b);
    float ch = fmaxf(y2a, y2b) - fminf(y1a, y1b);
    float diag = cw * cw + ch * ch + EPSV;
    float dx = (x1a + x2a) * 0.5f - (x1b + x2b) * 0.5f;
    float dy = (y1a + y2a) * 0.5f - (y1b + y2b) * 0.5f;
    float cent = dx * dx + dy * dy;

    float at = atanf((x2a - x1a) / (y2a - y1a + EPSV))
             - atanf((x2b - x1b) / (y2b - y1b + EPSV));
    const float C4PI2 = 4.0f / (float)(M_PI * M_PI);
    float v = C4PI2 * at * at;
    float alpha = v / (v - iou + 1.f + EPSV);
    return iou - (cent / diag + v * alpha);
}

// ---------------- kernel 1: per-target gather -> partials + tobj scatter ----
struct ScaleT {
    const float* box;   // [B,A,H,W,4]
    const float* cls;   // [B,A,H,W,80]
    const float* tbox;  // [n,4]
    const float* anc;   // [n,2]
    const int *b, *a, *gy, *gx, *tcls;
    int H, W;
    int tobj_off;
    float inv_n;        // 1/n
    float inv_ncls;     // 1/(n*80)
};

__global__ void __launch_bounds__(256) k_targets(ScaleT s0, ScaleT s1, ScaleT s2) {
    int w    = threadIdx.x >> 5;
    int lane = threadIdx.x & 31;
    int gw   = blockIdx.x * 8 + w;     // 1500*8 == 12000, no guard needed

    ScaleT s; int t;
    if (gw < N0)            { s = s0; t = gw; }
    else if (gw < N0 + N1)  { s = s1; t = gw - N0; }
    else                    { s = s2; t = gw - N0 - N1; }

    int base = ((s.b[t] * NA + s.a[t]) * s.H + s.gy[t]) * s.W + s.gx[t];

    // classification BCE across 80 classes (warp-parallel)
    int tc = s.tcls[t];
    const float* crow = s.cls + (size_t)base * NC;
    float csum = 0.f;
    #pragma unroll
    for (int c = lane; c < NC; c += 32)
        csum += bce_term(crow[c], (c == tc) ? 1.f : 0.f);
    #pragma unroll
    for (int o = 16; o; o >>= 1)
        csum += __shfl_down_sync(0xffffffffu, csum, o);

    __shared__ float sb[8], sc[8];
    if (lane == 0) {
        const float* br = s.box + (size_t)base * 4;
        float px = sigmoidf_(br[0]) * 2.f - 0.5f;
        float py = sigmoidf_(br[1]) * 2.f - 0.5f;
        float sw = sigmoidf_(br[2]) * 2.f;
        float sh = sigmoidf_(br[3]) * 2.f;
        float pw = sw * sw * s.anc[2 * t + 0];
        float ph = sh * sh * s.anc[2 * t + 1];

        const float* tb = s.tbox + 4 * t;
        float ci = ciou(px, py, pw, ph, tb[0], tb[1], tb[2], tb[3]);

        g_tobj[s.tobj_off + base] = fmaxf(ci, 0.f);   // races on dup cells: one wins (matches scatter-set)
        sb[w] = (1.f - ci) * s.inv_n;
        sc[w] = csum * s.inv_ncls;
    }
    __syncthreads();
    if (threadIdx.x == 0) {
        float pb = 0.f, pc = 0.f;
        #pragma unroll
        for (int i = 0; i < 8; i++) { pb += sb[i]; pc += sc[i]; }
        g_pb[blockIdx.x] = pb;
        g_pc[blockIdx.x] = pc;
    }
}

// ---------------- kernel 2: dense softplus + per-target linear correction --
// lobj = sum_dense softplus(x)*w  -  sum_{claimed cells} x*v*w
struct ObjP {
    const float *cnf0, *cnf1, *cnf2;
    const int *b0, *a0, *gy0, *gx0;
    const int *b1, *a1, *gy1, *gx1;
    const int *b2, *a2, *gy2, *gx2;
};

__global__ void __launch_bounds__(256) k_obj(ObjP p) {
    int i4 = blockIdx.x * 256 + threadIdx.x;
    float acc = 0.f;

    if (i4 < QTOT) {
        float4 x; float w;
        if (i4 < M0 / 4)                { x = ((const float4*)p.cnf0)[i4];               w = OBJ0 / (float)M0; }
        else if (i4 < (M0 + M1) / 4)    { x = ((const float4*)p.cnf1)[i4 - M0/4];        w = OBJ1 / (float)M1; }
        else                            { x = ((const float4*)p.cnf2)[i4 - (M0+M1)/4];   w = OBJ2 / (float)M2; }
        acc = (softplus_(x.x) + softplus_(x.y) + softplus_(x.z) + softplus_(x.w)) * w;
    }

    // correction for target cells (first 12000 global threads)
    if (i4 < NTGT_TOT) {
        const int *b, *a, *gy, *gx; const float* cnf;
        int t, H, W, off; float w;
        if (i4 < N0) {
            t = i4;            b = p.b0; a = p.a0; gy = p.gy0; gx = p.gx0;
            cnf = p.cnf0; H = H0; W = W0; off = 0;       w = OBJ0 / (float)M0;
        } else if (i4 < N0 + N1) {
            t = i4 - N0;       b = p.b1; a = p.a1; gy = p.gy1; gx = p.gx1;
            cnf = p.cnf1; H = H1; W = W1; off = M0;      w = OBJ1 / (float)M1;
        } else {
            t = i4 - N0 - N1;  b = p.b2; a = p.a2; gy = p.gy2; gx = p.gx2;
            cnf = p.cnf2; H = H2; W = W2; off = M0 + M1; w = OBJ2 / (float)M2;
        }
        int cell = ((b[t] * NA + a[t]) * H + gy[t]) * W + gx[t];
        float v = atomicExch(&g_tobj[off + cell], 0.f);  // claim + self-clean
        if (v != 0.f) acc -= cnf[cell] * v * w;
    }

    // block reduction
    #pragma unroll
    for (int o = 16; o; o >>= 1)
        acc += __shfl_down_sync(0xffffffffu, acc, o);
    __shared__ float sm[8];
    if ((threadIdx.x & 31) == 0) sm[threadIdx.x >> 5] = acc;
    __syncthreads();
    if (threadIdx.x == 0) {
        float s = 0.f;
        #pragma unroll
        for (int i = 0; i < 8; i++) s += sm[i];
        g_po[blockIdx.x] = s;
    }
}

// ---------------- kernel 3: final reduction over partials ----------------
__global__ void __launch_bounds__(1024) k_final(float* out) {
    int t = threadIdx.x;
    double db = 0.0, dc = 0.0, dob = 0.0;
    for (int i = t; i < TGT_BLOCKS; i += 1024) { db += (double)g_pb[i]; dc += (double)g_pc[i]; }
    for (int i = t; i < OBJ_BLOCKS; i += 1024) dob += (double)g_po[i];

    #pragma unroll
    for (int o = 16; o; o >>= 1) {
        db  += __shfl_down_sync(0xffffffffu, db,  o);
        dc  += __shfl_down_sync(0xffffffffu, dc,  o);
        dob += __shfl_down_sync(0xffffffffu, dob, o);
    }
    __shared__ double s0[32], s1[32], s2[32];
    int wid = t >> 5, lane = t & 31;
    if (lane == 0) { s0[wid] = db; s1[wid] = dc; s2[wid] = dob; }
    __syncthreads();
    if (wid == 0) {
        double b = s0[lane], c = s1[lane], o = s2[lane];
        #pragma unroll
        for (int of = 16; of; of >>= 1) {
            b += __shfl_down_sync(0xffffffffu, b, of);
            c += __shfl_down_sync(0xffffffffu, c, of);
            o += __shfl_down_sync(0xffffffffu, o, of);
        }
        if (lane == 0) {
            out[0] = (float)(b * 0.05 * 32.0);
            out[1] = (float)(o * 0.70 * 32.0);
            out[2] = (float)(c * 0.30 * 32.0);
        }
    }
}

// ---------------- launch ----------------
extern "C" void kernel_launch(void* const* d_in, const int* in_sizes, int n_in,
                              void* d_out, int out_size) {
    // Disambiguate metadata ordering via in_sizes[3] (see round-1 analysis):
    //  (A) reference-arg order -> in_sizes[3] == 24000 (tbox0)
    //  (B) setup_inputs insertion order per scale [box,cnf,cls,b,a,gy,gx,tcls,tbox,anc] -> 6000 (b0)
    const float *box[3], *cnf[3], *cls[3], *tbox[3], *anc[3];
    const int *bi[3], *ai[3], *gyi[3], *gxi[3], *tclsi[3];

    bool orderA = (n_in > 3 && in_sizes[3] == 24000);
    if (orderA) {
        for (int i = 0; i < 3; i++) {
            int f = 5 * i, g = 15 + 5 * i;
            box[i]   = (const float*)d_in[f + 0];
            cnf[i]   = (const float*)d_in[f + 1];
            cls[i]   = (const float*)d_in[f + 2];
            tbox[i]  = (const float*)d_in[f + 3];
            anc[i]   = (const float*)d_in[f + 4];
            bi[i]    = (const int*)d_in[g + 0];
            ai[i]    = (const int*)d_in[g + 1];
            gyi[i]   = (const int*)d_in[g + 2];
            gxi[i]   = (const int*)d_in[g + 3];
            tclsi[i] = (const int*)d_in[g + 4];
        }
    } else {
        for (int i = 0; i < 3; i++) {
            int p = 10 * i;
            box[i]   = (const float*)d_in[p + 0];
            cnf[i]   = (const float*)d_in[p + 1];
            cls[i]   = (const float*)d_in[p + 2];
            bi[i]    = (const int*)d_in[p + 3];
            ai[i]    = (const int*)d_in[p + 4];
            gyi[i]   = (const int*)d_in[p + 5];
            gxi[i]   = (const int*)d_in[p + 6];
            tclsi[i] = (const int*)d_in[p + 7];
            tbox[i]  = (const float*)d_in[p + 8];
            anc[i]   = (const float*)d_in[p + 9];
        }
    }

    ScaleT s0 { box[0], cls[0], tbox[0], anc[0], bi[0], ai[0], gyi[0], gxi[0], tclsi[0],
                H0, W0, 0,          1.f / N0, 1.f / (N0 * (float)NC) };
    ScaleT s1 { box[1], cls[1], tbox[1], anc[1], bi[1], ai[1], gyi[1], gxi[1], tclsi[1],
                H1, W1, M0,         1.f / N1, 1.f / (N1 * (float)NC) };
    ScaleT s2 { box[2], cls[2], tbox[2], anc[2], bi[2], ai[2], gyi[2], gxi[2], tclsi[2],
                H2, W2, M0 + M1,    1.f / N2, 1.f / (N2 * (float)NC) };

    ObjP op { cnf[0], cnf[1], cnf[2],
              bi[0], ai[0], gyi[0], gxi[0],
              bi[1], ai[1], gyi[1], gxi[1],
              bi[2], ai[2], gyi[2], gxi[2] };

    k_targets<<<TGT_BLOCKS, 256>>>(s0, s1, s2);
    k_obj<<<OBJ_BLOCKS, 256>>>(op);
    k_final<<<1, 1024>>>((float*)d_out);
}